// round 11
// baseline (speedup 1.0000x reference)
#include <cuda_runtime.h>
#include <cuda_bf16.h>

// ---------------------------------------------------------------------------
// ConvLSTM via mma.sync tf32 single-pass, fp32 accum. Round 11.
// Pair-interleaved channel layouts (c, c+4 adjacent) -> ld.shared.v2.b32
// halves LDS instructions in MMA loops. h stored permuted by step epilogue;
// U/W permuted in prep. ic A path unchanged (raw x, scalar lds + cvt).
// ---------------------------------------------------------------------------

#define H2 64
#define W2 64
#define FCH 64
#define BATCH 4
#define TSTEPS 16
#define NIMG 64

// xz blob: [img][mt32][nh2][warp8][frag64][lane32] floats
__device__ float g_xz[(size_t)NIMG * 32 * 2 * 8 * 64 * 32];          // 268 MB
__device__ float g_ut[9 * 256 * 64];     // [tap][n_perm][ci_pairperm], tf32
__device__ float g_wt[9 * 256 * 32];     // [tap][n_perm][ci_pairperm]
__device__ float g_bperm[256];
__device__ float g_ht[2][(size_t)BATCH * H2 * W2 * FCH];             // pair-perm
__device__ float g_c[(size_t)BATCH * H2 * W2 * FCH];

// ---------------- helpers ---------------------------------------------------
__device__ __forceinline__ unsigned smem_u32(const void* p) {
    return (unsigned)__cvta_generic_to_shared(p);
}
__device__ __forceinline__ void cp16p(unsigned dst, const void* src, bool p) {
    asm volatile("cp.async.cg.shared.global [%0], [%1], 16, %2;"
                 :: "r"(dst), "l"(src), "r"(p ? 16u : 0u));
}
#define CP_COMMIT() asm volatile("cp.async.commit_group;")
#define CP_WAIT0()  asm volatile("cp.async.wait_group 0;" ::: "memory")

__device__ __forceinline__ unsigned lds32(unsigned addr) {
    unsigned v;
    asm volatile("ld.shared.b32 %0, [%1];" : "=r"(v) : "r"(addr));
    return v;
}
__device__ __forceinline__ void lds64(unsigned& v0, unsigned& v1, unsigned addr) {
    asm volatile("ld.shared.v2.b32 {%0,%1}, [%2];"
                 : "=r"(v0), "=r"(v1) : "r"(addr));
}
__device__ __forceinline__ void mma_tf32(float c[4], const unsigned a[4],
                                         unsigned b0, unsigned b1) {
    asm volatile(
        "mma.sync.aligned.m16n8k8.row.col.f32.tf32.tf32.f32 "
        "{%0,%1,%2,%3}, {%4,%5,%6,%7}, {%8,%9}, {%0,%1,%2,%3};"
        : "+f"(c[0]), "+f"(c[1]), "+f"(c[2]), "+f"(c[3])
        : "r"(a[0]), "r"(a[1]), "r"(a[2]), "r"(a[3]), "r"(b0), "r"(b1));
}
__device__ __forceinline__ unsigned cvt_tf32u(unsigned v) {
    unsigned u;
    asm("cvt.rna.tf32.f32 %0, %1;" : "=r"(u) : "f"(__uint_as_float(v)));
    return u;
}
__device__ __forceinline__ float to_tf32(float v) {
    unsigned u;
    asm("cvt.rna.tf32.f32 %0, %1;" : "=r"(u) : "f"(v));
    return __uint_as_float(u);
}
__device__ __forceinline__ float hsig(float z) {
    return fminf(fmaxf(0.2f * z + 0.5f, 0.f), 1.f);
}

// perm v2 (cout -> n-row): cout = g*64+fc -> n = (fc>>3)*32 + g*8 + (fc&7)
__host__ __device__ __forceinline__ int perm_n(int cout) {
    int g = cout >> 6, fc = cout & 63;
    return (fc >> 3) * 32 + g * 8 + (fc & 7);
}
// pair-perm (channel position within a K-row): c=8k+j -> 8k + (j&3)*2 + (j>>2)
__host__ __device__ __forceinline__ int perm_pair(int c) {
    int k = c >> 3, j = c & 7;
    return k * 8 + (j & 3) * 2 + (j >> 2);
}

// step smem: A[0:46080) (180 rows x 256B), B stages 2 x 32768
#define SB_BASE 46080
#define SB_STAGE 32768
#define ST_SMEM (SB_BASE + 2 * SB_STAGE)     // 111616
// ic smem: A x-tile 561 rows x 128B = 71808; B stages 2 x 16384
#define ICB_BASE 71808
#define ICB_STAGE 16384
#define IC_SMEM (ICB_BASE + 2 * ICB_STAGE)   // 104576

// ---------------- prep ------------------------------------------------------
__global__ void prep_weights(const float* __restrict__ U,
                             const float* __restrict__ W,
                             const float* __restrict__ b) {
    int i = blockIdx.x * 256 + threadIdx.x;
    if (i < 9 * 64 * 256) {
        int tap = i / 16384, r = i % 16384, ci = r >> 8, cout = r & 255;
        g_ut[tap * 16384 + perm_n(cout) * 64 + perm_pair(ci)] = to_tf32(U[i]);
    }
    if (i < 9 * 32 * 256) {
        int tap = i / 8192, r = i % 8192, ci = r >> 8, cout = r & 255;
        g_wt[tap * 8192 + perm_n(cout) * 32 + perm_pair(ci)] = to_tf32(W[i]);
    }
    if (i < 256) g_bperm[perm_n(i)] = b[i];
}

// ---------------- input conv ------------------------------------------------
// A: x-tile 17x33 rows x 128B, 16B-granule swizzle key (row>>1)&7, staged once
// (raw fp32 x, scalar lds + in-register cvt). B: pair-perm rows, 8B-granule
// swizzle key (n&3), 2 stages, v2 loads.
__device__ __forceinline__ void fill_icb(unsigned dst, int tap, int nh, int tid) {
    const float* wt = g_wt + tap * 8192 + nh * 128 * 32;
    for (int i = tid; i < 1024; i += 256) {
        int n = i >> 3, cc = i & 7;
        cp16p(dst + n * 128 + (((2 * cc) ^ ((n & 3) << 2)) << 3),
              wt + n * 32 + cc * 4, true);
    }
    CP_COMMIT();
}

__global__ __launch_bounds__(256, 2) void ic_mma_kernel(
    const float* __restrict__ x, float* __restrict__ xz)
{
    extern __shared__ __align__(1024) char smem[];
    unsigned sb = smem_u32(smem);
    const int tid = threadIdx.x, lane = tid & 31, wid = tid >> 5;
    const int mw = wid >> 2, nw = wid & 3;
    const int r = lane >> 2, cq = lane & 3;
    const int mt = blockIdx.x;
    const int img = blockIdx.y >> 1, nh = blockIdx.y & 1;
    const int oh0 = (mt >> 2) * 8, ow0 = (mt & 3) * 16;
    const int ih0 = 2 * oh0, iw0 = 2 * ow0;

    // A fill: 561 tile-rows x 8 chunks, raw fp32 x, zero-fill OOB
    for (int i = tid; i < 4488; i += 256) {
        int row = i >> 3, cc = i & 7;
        int trow = row / 33, tcol = row - trow * 33;
        int ih = ih0 + trow, iw = iw0 + tcol;
        bool ok = (ih < 128 && iw < 128);
        const float* s = x +
            (((size_t)img * 128 + (ok ? ih : 0)) * 128 + (ok ? iw : 0)) * 32 + cc * 4;
        cp16p(sb + row * 128 + ((cc ^ ((row >> 1) & 7)) << 4), s, ok);
    }
    fill_icb(sb + ICB_BASE, 0, nh, tid);     // commits A + B0 together

    // B pair addressing: key = n&3 = r&3
    unsigned nbase[4];
#pragma unroll
    for (int nf = 0; nf < 4; nf++)
        nbase[nf] = (unsigned)((nw * 32 + nf * 8 + r) * 128 + cq * 8);
    const int bkey = r & 3;

    float acc[4][4][4];
#pragma unroll
    for (int a = 0; a < 4; a++)
#pragma unroll
        for (int b = 0; b < 4; b++)
#pragma unroll
            for (int c = 0; c < 4; c++) acc[a][b][c] = 0.f;

    for (int tap = 0; tap < 9; tap++) {
        CP_WAIT0();
        __syncthreads();
        if (tap < 8)
            fill_icb(sb + ICB_BASE + ((tap + 1) & 1) * ICB_STAGE, tap + 1, nh, tid);
        const int kh = tap / 3, kw = tap - kh * 3;
        unsigned Bst = sb + ICB_BASE + (tap & 1) * ICB_STAGE;

        unsigned abase[4];
        int akey[4];
#pragma unroll
        for (int mf = 0; mf < 4; mf++) {
            int row0 = (2 * (mw * 4 + mf) + kh) * 33 + (2 * r + kw);
            abase[mf] = sb + (unsigned)(row0 * 128 + cq * 4);
            akey[mf] = (row0 >> 1) & 7;      // same key for row0+16
        }

#pragma unroll
        for (int k = 0; k < 4; k++) {
            unsigned av[4][4], bv[4][2];
#pragma unroll
            for (int mf = 0; mf < 4; mf++) {
                unsigned o0 = (unsigned)(((2 * k) ^ akey[mf]) << 4);
                av[mf][0] = cvt_tf32u(lds32(abase[mf] + o0));
                av[mf][1] = cvt_tf32u(lds32(abase[mf] + o0 + 2048));  // sc +8
                av[mf][2] = cvt_tf32u(lds32(abase[mf] + (o0 ^ 16)));
                av[mf][3] = cvt_tf32u(lds32(abase[mf] + (o0 ^ 16) + 2048));
            }
            {
                unsigned off = (unsigned)((k ^ bkey) * 32);
#pragma unroll
                for (int nf = 0; nf < 4; nf++)
                    lds64(bv[nf][0], bv[nf][1], Bst + nbase[nf] + off);
            }
#pragma unroll
            for (int mf = 0; mf < 4; mf++)
#pragma unroll
                for (int nf = 0; nf < 4; nf++)
                    mma_tf32(acc[mf][nf], av[mf], bv[nf][0], bv[nf][1]);
        }
    }

    // epilogue: +bias(perm), write fragment blob
    float2 bvq[4];
#pragma unroll
    for (int nf = 0; nf < 4; nf++)
        bvq[nf] = *(const float2*)(g_bperm + nh * 128 + nw * 32 + nf * 8 + 2 * cq);
    float* blob = xz + ((((size_t)img * 32 + mt) * 2 + nh) * 8 + wid) * 2048 + lane;
#pragma unroll
    for (int mf = 0; mf < 4; mf++)
#pragma unroll
        for (int nf = 0; nf < 4; nf++)
#pragma unroll
            for (int rg = 0; rg < 4; rg++)
                blob[((mf * 4 + nf) * 4 + rg) * 32] =
                    acc[mf][nf][rg] + ((rg & 1) ? bvq[nf].y : bvq[nf].x);
}

// ---------------- LSTM step -------------------------------------------------
// A (h) and B (U) pair-permuted; 8B-granule swizzle key row&7 / n&7; v2 loads.
__device__ __forceinline__ void fill_b_step(unsigned dst, int tap, int nh, int tid) {
    const float* ut = g_ut + tap * 16384 + nh * 128 * 64;
    for (int i = tid; i < 2048; i += 256) {
        int n = i >> 4, cc = i & 15;
        cp16p(dst + n * 256 + (((2 * cc) ^ ((n & 7) << 2)) << 3),
              ut + n * 64 + cc * 4, true);
    }
    CP_COMMIT();
}

__global__ __launch_bounds__(256, 2) void lstm_step_mma(
    const float* __restrict__ hin, float* __restrict__ hout,
    float* __restrict__ cbuf, const float* __restrict__ xz,
    const float* __restrict__ gamma, const float* __restrict__ beta,
    const float* __restrict__ mmean, const float* __restrict__ mvar,
    float* __restrict__ out, int t)
{
    extern __shared__ __align__(1024) char smem[];
    unsigned sb = smem_u32(smem);
    const int tid = threadIdx.x, lane = tid & 31, wid = tid >> 5;
    const int mw = wid >> 2, nw = wid & 3;
    const int r = lane >> 2, cq = lane & 3;
    const int mt = blockIdx.x;
    const int bb = blockIdx.y >> 1, nh = blockIdx.y & 1;
    const int oh0 = (mt >> 2) * 8, ow0 = (mt & 3) * 16;

    // A: halo'd h tile 10x18 rows x 256B (pair-perm channels), key row&7; once
    for (int i = tid; i < 2880; i += 256) {
        int row = i >> 4, cc = i & 15;
        int sr = row / 18, sc = row - sr * 18;
        int ih = oh0 - 1 + sr, iw = ow0 - 1 + sc;
        bool ok = (ih >= 0 && ih < H2 && iw >= 0 && iw < W2);
        const float* s = hin +
            (((size_t)bb * H2 + (ok ? ih : 0)) * W2 + (ok ? iw : 0)) * FCH + cc * 4;
        cp16p(sb + row * 256 + (((2 * cc) ^ ((row & 7) << 2)) << 3), s, ok);
    }
    fill_b_step(sb + SB_BASE, 0, nh, tid);   // commits A + B0 together

    unsigned nbase[4];
#pragma unroll
    for (int nf = 0; nf < 4; nf++)
        nbase[nf] = (unsigned)((nw * 32 + nf * 8 + r) * 256 + cq * 8);
    // B key = n&7 = r

    float acc[4][4][4];
#pragma unroll
    for (int a = 0; a < 4; a++)
#pragma unroll
        for (int b = 0; b < 4; b++)
#pragma unroll
            for (int c = 0; c < 4; c++) acc[a][b][c] = 0.f;

    for (int tap = 0; tap < 9; tap++) {
        CP_WAIT0();
        __syncthreads();
        if (tap < 8)
            fill_b_step(sb + SB_BASE + ((tap + 1) & 1) * SB_STAGE, tap + 1, nh, tid);
        const int kh = tap / 3, kw = tap - kh * 3;
        unsigned Bst = sb + SB_BASE + (tap & 1) * SB_STAGE;

        unsigned abase[4];
        int ar7[4];
#pragma unroll
        for (int mf = 0; mf < 4; mf++) {
            int row0 = (mw * 4 + mf + kh) * 18 + r + kw;
            abase[mf] = sb + (unsigned)(row0 * 256 + cq * 8);
            ar7[mf] = row0 & 7;              // same key for row0+8
        }

#pragma unroll
        for (int k = 0; k < 8; k++) {
            unsigned av[4][4], bv[4][2];
#pragma unroll
            for (int mf = 0; mf < 4; mf++) {
                unsigned off = (unsigned)((k ^ ar7[mf]) * 32);
                lds64(av[mf][0], av[mf][2], abase[mf] + off);
                lds64(av[mf][1], av[mf][3], abase[mf] + off + 2048);  // ow +8
            }
            {
                unsigned off = (unsigned)((k ^ r) * 32);
#pragma unroll
                for (int nf = 0; nf < 4; nf++)
                    lds64(bv[nf][0], bv[nf][1], Bst + nbase[nf] + off);
            }
#pragma unroll
            for (int mf = 0; mf < 4; mf++)
#pragma unroll
                for (int nf = 0; nf < 4; nf++)
                    mma_tf32(acc[mf][nf], av[mf], bv[nf][0], bv[nf][1]);
        }
    }

    // add xz (bias folded)
    const float* blob = xz +
        ((((size_t)(bb * TSTEPS + t) * 32 + mt) * 2 + nh) * 8 + wid) * 2048 + lane;
#pragma unroll
    for (int mf = 0; mf < 4; mf++)
#pragma unroll
        for (int nf = 0; nf < 4; nf++)
#pragma unroll
            for (int rg = 0; rg < 4; rg++)
                acc[mf][nf][rg] += blob[((mf * 4 + nf) * 4 + rg) * 32];

    // gates in-register: nf = gate; lane fc pair fc0, fc0+1
    const int fc0 = (nh * 4 + nw) * 8 + 2 * cq;
    // pair-perm positions of fc0, fc0+1 within the 64-ch block
    const int hp0 = (nh * 4 + nw) * 8 + ((2 * cq) & 3) * 2 + ((2 * cq) >> 2);
    const int hp1 = (nh * 4 + nw) * 8 + ((2 * cq + 1) & 3) * 2 + ((2 * cq + 1) >> 2);
    float2 gm = *(const float2*)(gamma + fc0);
    float2 bt = *(const float2*)(beta + fc0);
    float2 mu = *(const float2*)(mmean + fc0);
    float2 vr = *(const float2*)(mvar + fc0);
    float sc0 = gm.x * rsqrtf(vr.x + 1e-3f);
    float sc1 = gm.y * rsqrtf(vr.y + 1e-3f);

#pragma unroll
    for (int mf = 0; mf < 4; mf++) {
        int oh = oh0 + mw * 4 + mf;
#pragma unroll
        for (int rh = 0; rh < 2; rh++) {
            int ow = ow0 + r + 8 * rh;
            size_t pbase = ((size_t)bb * H2 + oh) * W2 + ow;
            size_t sidx = pbase * FCH + fc0;
            float2 cc2 = *(const float2*)(cbuf + sidx);
            float cn[2], hn[2], ov[2];
#pragma unroll
            for (int q = 0; q < 2; q++) {
                float zi = acc[mf][0][2 * rh + q];
                float zf = acc[mf][1][2 * rh + q];
                float zg = acc[mf][2][2 * rh + q];
                float zo = acc[mf][3][2 * rh + q];
                float co = q ? cc2.y : cc2.x;
                float c2 = hsig(zf) * co + hsig(zi) * tanhf(zg);
                hn[q] = hsig(zo) * tanhf(c2);
                cn[q] = c2;
                float s = q ? sc1 : sc0;
                ov[q] = (hn[q] - (q ? mu.y : mu.x)) * s + (q ? bt.y : bt.x);
            }
            *(float2*)(cbuf + sidx) = make_float2(cn[0], cn[1]);
            // h stored tf32-rounded in pair-perm layout for next step's A fill
            hout[pbase * FCH + hp0] = to_tf32(hn[0]);
            hout[pbase * FCH + hp1] = to_tf32(hn[1]);
            *(float2*)(out + ((((size_t)bb * TSTEPS + t) * H2 + oh) * W2 + ow) * FCH + fc0)
                = make_float2(ov[0], ov[1]);
        }
    }
}

// ---------------------------------------------------------------------------
extern "C" void kernel_launch(void* const* d_in, const int* in_sizes, int n_in,
                              void* d_out, int out_size)
{
    const float* x     = (const float*)d_in[0];
    const float* W     = (const float*)d_in[1];
    const float* U     = (const float*)d_in[2];
    const float* b     = (const float*)d_in[3];
    const float* gamma = (const float*)d_in[4];
    const float* beta  = (const float*)d_in[5];
    const float* mm    = (const float*)d_in[6];
    const float* mv    = (const float*)d_in[7];
    float* out = (float*)d_out;

    float *xz, *cbuf, *hbuf;
    cudaGetSymbolAddress((void**)&xz, g_xz);
    cudaGetSymbolAddress((void**)&cbuf, g_c);
    cudaGetSymbolAddress((void**)&hbuf, g_ht);
    const size_t hsz = (size_t)BATCH * H2 * W2 * FCH;

    cudaFuncSetAttribute(ic_mma_kernel,
                         cudaFuncAttributeMaxDynamicSharedMemorySize, IC_SMEM);
    cudaFuncSetAttribute(lstm_step_mma,
                         cudaFuncAttributeMaxDynamicSharedMemorySize, ST_SMEM);

    cudaMemsetAsync(hbuf, 0, hsz * sizeof(float));
    cudaMemsetAsync(cbuf, 0, hsz * sizeof(float));

    prep_weights<<<576, 256>>>(U, W, b);
    ic_mma_kernel<<<dim3(32, 128), 256, IC_SMEM>>>(x, xz);

    for (int t = 0; t < TSTEPS; t++) {
        int rd = t & 1, wr = (t + 1) & 1;
        lstm_step_mma<<<dim3(32, 8), 256, ST_SMEM>>>(
            hbuf + rd * hsz, hbuf + wr * hsz,
            cbuf, xz, gamma, beta, mm, mv, out, t);
    }
}

// round 12
// speedup vs baseline: 1.4467x; 1.4467x over previous
#include <cuda_runtime.h>
#include <cuda_bf16.h>

// ---------------------------------------------------------------------------
// ConvLSTM via mma.sync tf32 single-pass, fp32 accum. Round 12.
// R10 base (proven 847us) + step kernel rebalanced to m64xn64 warp tiles:
// 4 warps/CTA, nf=8 -> 128B LDS per HMMA (was 192). Accumulation order
// unchanged -> bitwise-identical numerics to R10.
// ---------------------------------------------------------------------------

#define H2 64
#define W2 64
#define FCH 64
#define BATCH 4
#define TSTEPS 16
#define NIMG 64

// xz blob (step-canonical): [img][mt32][nh2][warp4][frag128][lane32] floats
__device__ float g_xz[(size_t)NIMG * 32 * 2 * 4 * 128 * 32];         // 268 MB
__device__ float g_ut[9 * 256 * 64];     // [tap][n_perm][ci], tf32-rounded
__device__ float g_wt[9 * 256 * 32];     // [tap][n_perm][ci]
__device__ float g_bperm[256];
__device__ float g_ht[2][(size_t)BATCH * H2 * W2 * FCH];             // 2 x 4 MB
__device__ float g_c[(size_t)BATCH * H2 * W2 * FCH];

// ---------------- helpers ---------------------------------------------------
__device__ __forceinline__ unsigned smem_u32(const void* p) {
    return (unsigned)__cvta_generic_to_shared(p);
}
__device__ __forceinline__ void cp16p(unsigned dst, const void* src, bool p) {
    asm volatile("cp.async.cg.shared.global [%0], [%1], 16, %2;"
                 :: "r"(dst), "l"(src), "r"(p ? 16u : 0u));
}
#define CP_COMMIT() asm volatile("cp.async.commit_group;")
#define CP_WAIT0()  asm volatile("cp.async.wait_group 0;" ::: "memory")

__device__ __forceinline__ unsigned lds32(unsigned addr) {
    unsigned v;
    asm volatile("ld.shared.b32 %0, [%1];" : "=r"(v) : "r"(addr));
    return v;
}
__device__ __forceinline__ void mma_tf32(float c[4], const unsigned a[4],
                                         unsigned b0, unsigned b1) {
    asm volatile(
        "mma.sync.aligned.m16n8k8.row.col.f32.tf32.tf32.f32 "
        "{%0,%1,%2,%3}, {%4,%5,%6,%7}, {%8,%9}, {%0,%1,%2,%3};"
        : "+f"(c[0]), "+f"(c[1]), "+f"(c[2]), "+f"(c[3])
        : "r"(a[0]), "r"(a[1]), "r"(a[2]), "r"(a[3]), "r"(b0), "r"(b1));
}
__device__ __forceinline__ unsigned cvt_tf32u(unsigned v) {
    unsigned u;
    asm("cvt.rna.tf32.f32 %0, %1;" : "=r"(u) : "f"(__uint_as_float(v)));
    return u;
}
__device__ __forceinline__ float to_tf32(float v) {
    unsigned u;
    asm("cvt.rna.tf32.f32 %0, %1;" : "=r"(u) : "f"(v));
    return __uint_as_float(u);
}
__device__ __forceinline__ float hsig(float z) {
    return fminf(fmaxf(0.2f * z + 0.5f, 0.f), 1.f);
}

// perm v2: cout = g*64+fc -> n = (fc>>3)*32 + g*8 + (fc&7)
__host__ __device__ __forceinline__ int perm_n(int cout) {
    int g = cout >> 6, fc = cout & 63;
    return (fc >> 3) * 32 + g * 8 + (fc & 7);
}

// step smem: A[0:46080) (180 rows x 256B, swizzled), B stages 2 x 32768
#define SB_BASE 46080
#define SB_STAGE 32768
#define ST_SMEM (SB_BASE + 2 * SB_STAGE)     // 111616
// ic smem: A x-tile 561 rows x 128B = 71808; B stages 2 x 16384
#define ICB_BASE 71808
#define ICB_STAGE 16384
#define IC_SMEM (ICB_BASE + 2 * ICB_STAGE)   // 104576

// ---------------- prep ------------------------------------------------------
__global__ void prep_weights(const float* __restrict__ U,
                             const float* __restrict__ W,
                             const float* __restrict__ b) {
    int i = blockIdx.x * 256 + threadIdx.x;
    if (i < 9 * 64 * 256) {
        int tap = i / 16384, r = i % 16384, ci = r >> 8, cout = r & 255;
        g_ut[tap * 16384 + perm_n(cout) * 64 + ci] = to_tf32(U[i]);
    }
    if (i < 9 * 32 * 256) {
        int tap = i / 8192, r = i % 8192, ci = r >> 8, cout = r & 255;
        g_wt[tap * 8192 + perm_n(cout) * 32 + ci] = to_tf32(W[i]);
    }
    if (i < 256) g_bperm[perm_n(i)] = b[i];
}

// ---------------- input conv (R10 internals; blob write re-indexed) ---------
__device__ __forceinline__ void fill_icb(unsigned dst, int tap, int nh, int tid) {
    const float* wt = g_wt + tap * 8192 + nh * 128 * 32;
    for (int i = tid; i < 1024; i += 256) {
        int n = i >> 3, cc = i & 7;
        cp16p(dst + n * 128 + ((cc ^ (n & 7)) << 4), wt + n * 32 + cc * 4, true);
    }
    CP_COMMIT();
}

__global__ __launch_bounds__(256, 2) void ic_mma_kernel(
    const float* __restrict__ x, float* __restrict__ xz)
{
    extern __shared__ __align__(1024) char smem[];
    unsigned sb = smem_u32(smem);
    const int tid = threadIdx.x, lane = tid & 31, wid = tid >> 5;
    const int mw = wid >> 2, nw = wid & 3;
    const int r = lane >> 2, cq = lane & 3;
    const int mt = blockIdx.x;
    const int img = blockIdx.y >> 1, nh = blockIdx.y & 1;
    const int oh0 = (mt >> 2) * 8, ow0 = (mt & 3) * 16;
    const int ih0 = 2 * oh0, iw0 = 2 * ow0;

    // A fill: 561 tile-rows x 8 chunks, raw fp32 x, zero-fill OOB
    for (int i = tid; i < 4488; i += 256) {
        int row = i >> 3, cc = i & 7;
        int trow = row / 33, tcol = row - trow * 33;
        int ih = ih0 + trow, iw = iw0 + tcol;
        bool ok = (ih < 128 && iw < 128);
        const float* s = x +
            (((size_t)img * 128 + (ok ? ih : 0)) * 128 + (ok ? iw : 0)) * 32 + cc * 4;
        cp16p(sb + row * 128 + ((cc ^ ((row >> 1) & 7)) << 4), s, ok);
    }
    fill_icb(sb + ICB_BASE, 0, nh, tid);     // commits A + B0 together

    unsigned nbase[4];
#pragma unroll
    for (int nf = 0; nf < 4; nf++)
        nbase[nf] = (unsigned)((nw * 32 + nf * 8 + r) * 128 + cq * 4);

    float acc[4][4][4];
#pragma unroll
    for (int a = 0; a < 4; a++)
#pragma unroll
        for (int b = 0; b < 4; b++)
#pragma unroll
            for (int c = 0; c < 4; c++) acc[a][b][c] = 0.f;

    for (int tap = 0; tap < 9; tap++) {
        CP_WAIT0();
        __syncthreads();
        if (tap < 8)
            fill_icb(sb + ICB_BASE + ((tap + 1) & 1) * ICB_STAGE, tap + 1, nh, tid);
        const int kh = tap / 3, kw = tap - kh * 3;
        unsigned Bst = sb + ICB_BASE + (tap & 1) * ICB_STAGE;

        unsigned abase[4];
        int akey[4];
#pragma unroll
        for (int mf = 0; mf < 4; mf++) {
            int row0 = (2 * (mw * 4 + mf) + kh) * 33 + (2 * r + kw);
            abase[mf] = sb + (unsigned)(row0 * 128 + cq * 4);
            akey[mf] = (row0 >> 1) & 7;      // same key for row0+16
        }

#pragma unroll
        for (int k = 0; k < 4; k++) {
            unsigned av[4][4], bv[4][2];
#pragma unroll
            for (int mf = 0; mf < 4; mf++) {
                unsigned o0 = (unsigned)(((2 * k) ^ akey[mf]) << 4);
                av[mf][0] = cvt_tf32u(lds32(abase[mf] + o0));
                av[mf][1] = cvt_tf32u(lds32(abase[mf] + o0 + 2048));  // sc +8
                av[mf][2] = cvt_tf32u(lds32(abase[mf] + (o0 ^ 16)));
                av[mf][3] = cvt_tf32u(lds32(abase[mf] + (o0 ^ 16) + 2048));
            }
            {
                unsigned o0 = (unsigned)(((2 * k) ^ r) << 4);   // B row&7 == r
#pragma unroll
                for (int nf = 0; nf < 4; nf++) {
                    bv[nf][0] = lds32(Bst + nbase[nf] + o0);
                    bv[nf][1] = lds32(Bst + nbase[nf] + (o0 ^ 16));
                }
            }
#pragma unroll
            for (int mf = 0; mf < 4; mf++)
#pragma unroll
                for (int nf = 0; nf < 4; nf++)
                    mma_tf32(acc[mf][nf], av[mf], bv[nf][0], bv[nf][1]);
        }
    }

    // epilogue: +bias(perm), write blob in STEP-canonical 4-warp layout:
    // w_st = mw*2 + (nw>>1); nf_st = (nw&1)*4 + nf; frag = (mf*8+nf_st)*4+rg
    float2 bvq[4];
#pragma unroll
    for (int nf = 0; nf < 4; nf++)
        bvq[nf] = *(const float2*)(g_bperm + nh * 128 + nw * 32 + nf * 8 + 2 * cq);
    const int w_st = mw * 2 + (nw >> 1);
    float* blob = xz + ((((size_t)img * 32 + mt) * 2 + nh) * 4 + w_st) * 4096 + lane;
#pragma unroll
    for (int mf = 0; mf < 4; mf++)
#pragma unroll
        for (int nf = 0; nf < 4; nf++) {
            int nf_st = (nw & 1) * 4 + nf;
#pragma unroll
            for (int rg = 0; rg < 4; rg++)
                blob[((mf * 8 + nf_st) * 4 + rg) * 32] =
                    acc[mf][nf][rg] + ((rg & 1) ? bvq[nf].y : bvq[nf].x);
        }
}

// ---------------- LSTM step: 4 warps, m64 x n64 per warp --------------------
__device__ __forceinline__ void fill_b_step(unsigned dst, int tap, int nh, int tid) {
    const float* ut = g_ut + tap * 16384 + nh * 128 * 64;
    for (int i = tid; i < 2048; i += 128) {
        int n = i >> 4, cc = i & 15;
        cp16p(dst + n * 256 + ((cc ^ (n & 7)) << 4), ut + n * 64 + cc * 4, true);
    }
    CP_COMMIT();
}

__global__ __launch_bounds__(128, 2) void lstm_step_mma(
    const float* __restrict__ hin, float* __restrict__ hout,
    float* __restrict__ cbuf, const float* __restrict__ xz,
    const float* __restrict__ gamma, const float* __restrict__ beta,
    const float* __restrict__ mmean, const float* __restrict__ mvar,
    float* __restrict__ out, int t)
{
    extern __shared__ __align__(1024) char smem[];
    unsigned sb = smem_u32(smem);
    const int tid = threadIdx.x, lane = tid & 31, wid = tid >> 5;
    const int mw = wid >> 1, nw = wid & 1;
    const int r = lane >> 2, cq = lane & 3;
    const int mt = blockIdx.x;
    const int bb = blockIdx.y >> 1, nh = blockIdx.y & 1;
    const int oh0 = (mt >> 2) * 8, ow0 = (mt & 3) * 16;

    // A: halo'd h tile 10x18 spatial rows x 256B (64ch fp32), swizzled; once
    for (int i = tid; i < 2880; i += 128) {
        int row = i >> 4, cc = i & 15;
        int sr = row / 18, sc = row - sr * 18;
        int ih = oh0 - 1 + sr, iw = ow0 - 1 + sc;
        bool ok = (ih >= 0 && ih < H2 && iw >= 0 && iw < W2);
        const float* s = hin +
            (((size_t)bb * H2 + (ok ? ih : 0)) * W2 + (ok ? iw : 0)) * FCH + cc * 4;
        cp16p(sb + row * 256 + ((cc ^ (row & 7)) << 4), s, ok);
    }
    fill_b_step(sb + SB_BASE, 0, nh, tid);   // commits A + B0 together

    unsigned nbase[8];
#pragma unroll
    for (int nf = 0; nf < 8; nf++)
        nbase[nf] = (unsigned)((nw * 64 + nf * 8 + r) * 256 + cq * 4);

    float acc[4][8][4];
#pragma unroll
    for (int a = 0; a < 4; a++)
#pragma unroll
        for (int b = 0; b < 8; b++)
#pragma unroll
            for (int c = 0; c < 4; c++) acc[a][b][c] = 0.f;

    for (int tap = 0; tap < 9; tap++) {
        CP_WAIT0();
        __syncthreads();
        if (tap < 8)
            fill_b_step(sb + SB_BASE + ((tap + 1) & 1) * SB_STAGE, tap + 1, nh, tid);
        const int kh = tap / 3, kw = tap - kh * 3;
        unsigned Bst = sb + SB_BASE + (tap & 1) * SB_STAGE;

        unsigned abase[4];
        int ar7[4];
#pragma unroll
        for (int mf = 0; mf < 4; mf++) {
            int row0 = (mw * 4 + mf + kh) * 18 + r + kw;
            abase[mf] = sb + (unsigned)(row0 * 256 + cq * 4);
            ar7[mf] = row0 & 7;
        }

#pragma unroll
        for (int k = 0; k < 8; k++) {
            unsigned av[4][4], bv[8][2];
#pragma unroll
            for (int mf = 0; mf < 4; mf++) {
                unsigned o0 = (unsigned)(((2 * k) ^ ar7[mf]) << 4);
                av[mf][0] = lds32(abase[mf] + o0);
                av[mf][1] = lds32(abase[mf] + o0 + 2048);       // ow +8
                av[mf][2] = lds32(abase[mf] + (o0 ^ 16));
                av[mf][3] = lds32(abase[mf] + (o0 ^ 16) + 2048);
            }
            {
                unsigned o0 = (unsigned)(((2 * k) ^ r) << 4);   // n&7 == r
#pragma unroll
                for (int nf = 0; nf < 8; nf++) {
                    bv[nf][0] = lds32(Bst + nbase[nf] + o0);
                    bv[nf][1] = lds32(Bst + nbase[nf] + (o0 ^ 16));
                }
            }
#pragma unroll
            for (int mf = 0; mf < 4; mf++)
#pragma unroll
                for (int nf = 0; nf < 8; nf++)
                    mma_tf32(acc[mf][nf], av[mf], bv[nf][0], bv[nf][1]);
        }
    }

    // add xz (bias folded), step-canonical blob layout
    const float* blob = xz +
        ((((size_t)(bb * TSTEPS + t) * 32 + mt) * 2 + nh) * 4 + wid) * 4096 + lane;
#pragma unroll
    for (int mf = 0; mf < 4; mf++)
#pragma unroll
        for (int nf = 0; nf < 8; nf++)
#pragma unroll
            for (int rg = 0; rg < 4; rg++)
                acc[mf][nf][rg] += blob[((mf * 8 + nf) * 4 + rg) * 32];

    // gates in-register: nf = fh*4 + gate; fc0 = (nh*4 + nw*2 + fh)*8 + 2cq
#pragma unroll
    for (int fh = 0; fh < 2; fh++) {
        const int fc0 = (nh * 4 + nw * 2 + fh) * 8 + 2 * cq;
        float2 gm = *(const float2*)(gamma + fc0);
        float2 bt = *(const float2*)(beta + fc0);
        float2 mu = *(const float2*)(mmean + fc0);
        float2 vr = *(const float2*)(mvar + fc0);
        float sc0 = gm.x * rsqrtf(vr.x + 1e-3f);
        float sc1 = gm.y * rsqrtf(vr.y + 1e-3f);

#pragma unroll
        for (int mf = 0; mf < 4; mf++) {
            int oh = oh0 + mw * 4 + mf;
#pragma unroll
            for (int rh = 0; rh < 2; rh++) {
                int ow = ow0 + r + 8 * rh;
                size_t sidx = (((size_t)bb * H2 + oh) * W2 + ow) * FCH + fc0;
                float2 cc2 = *(const float2*)(cbuf + sidx);
                float cn[2], hn[2], ov[2];
#pragma unroll
                for (int q = 0; q < 2; q++) {
                    float zi = acc[mf][fh * 4 + 0][2 * rh + q];
                    float zf = acc[mf][fh * 4 + 1][2 * rh + q];
                    float zg = acc[mf][fh * 4 + 2][2 * rh + q];
                    float zo = acc[mf][fh * 4 + 3][2 * rh + q];
                    float co = q ? cc2.y : cc2.x;
                    float c2 = hsig(zf) * co + hsig(zi) * tanhf(zg);
                    hn[q] = hsig(zo) * tanhf(c2);
                    cn[q] = c2;
                    float s = q ? sc1 : sc0;
                    ov[q] = (hn[q] - (q ? mu.y : mu.x)) * s + (q ? bt.y : bt.x);
                }
                *(float2*)(cbuf + sidx) = make_float2(cn[0], cn[1]);
                *(float2*)(hout + sidx) = make_float2(to_tf32(hn[0]), to_tf32(hn[1]));
                *(float2*)(out + ((((size_t)bb * TSTEPS + t) * H2 + oh) * W2 + ow) * FCH + fc0)
                    = make_float2(ov[0], ov[1]);
            }
        }
    }
}

// ---------------------------------------------------------------------------
extern "C" void kernel_launch(void* const* d_in, const int* in_sizes, int n_in,
                              void* d_out, int out_size)
{
    const float* x     = (const float*)d_in[0];
    const float* W     = (const float*)d_in[1];
    const float* U     = (const float*)d_in[2];
    const float* b     = (const float*)d_in[3];
    const float* gamma = (const float*)d_in[4];
    const float* beta  = (const float*)d_in[5];
    const float* mm    = (const float*)d_in[6];
    const float* mv    = (const float*)d_in[7];
    float* out = (float*)d_out;

    float *xz, *cbuf, *hbuf;
    cudaGetSymbolAddress((void**)&xz, g_xz);
    cudaGetSymbolAddress((void**)&cbuf, g_c);
    cudaGetSymbolAddress((void**)&hbuf, g_ht);
    const size_t hsz = (size_t)BATCH * H2 * W2 * FCH;

    cudaFuncSetAttribute(ic_mma_kernel,
                         cudaFuncAttributeMaxDynamicSharedMemorySize, IC_SMEM);
    cudaFuncSetAttribute(lstm_step_mma,
                         cudaFuncAttributeMaxDynamicSharedMemorySize, ST_SMEM);

    cudaMemsetAsync(hbuf, 0, hsz * sizeof(float));
    cudaMemsetAsync(cbuf, 0, hsz * sizeof(float));

    prep_weights<<<576, 256>>>(U, W, b);
    ic_mma_kernel<<<dim3(32, 128), 256, IC_SMEM>>>(x, xz);

    for (int t = 0; t < TSTEPS; t++) {
        int rd = t & 1, wr = (t + 1) & 1;
        lstm_step_mma<<<dim3(32, 8), 128, ST_SMEM>>>(
            hbuf + rd * hsz, hbuf + wr * hsz,
            cbuf, xz, gamma, beta, mm, mv, out, t);
    }
}

// round 13
// speedup vs baseline: 1.4929x; 1.0319x over previous
#include <cuda_runtime.h>
#include <cuda_bf16.h>

// ---------------------------------------------------------------------------
// ConvLSTM via mma.sync tf32 single-pass, fp32 accum. Round 13.
// R10 base (proven 847us); step kernel only change: per-pair B staging with
// producer warp + named barriers instead of per-tap CTA-wide syncs.
// ---------------------------------------------------------------------------

#define H2 64
#define W2 64
#define FCH 64
#define BATCH 4
#define TSTEPS 16
#define NIMG 64

// xz blob: [img][mt32][nh2][warp8][frag64][lane32] floats
__device__ float g_xz[(size_t)NIMG * 32 * 2 * 8 * 64 * 32];          // 268 MB
__device__ float g_ut[9 * 256 * 64];     // [tap][n_perm][ci], tf32-rounded
__device__ float g_wt[9 * 256 * 32];     // [tap][n_perm][ci]
__device__ float g_bperm[256];
__device__ float g_ht[2][(size_t)BATCH * H2 * W2 * FCH];             // 2 x 4 MB
__device__ float g_c[(size_t)BATCH * H2 * W2 * FCH];

// ---------------- helpers ---------------------------------------------------
__device__ __forceinline__ unsigned smem_u32(const void* p) {
    return (unsigned)__cvta_generic_to_shared(p);
}
__device__ __forceinline__ void cp16p(unsigned dst, const void* src, bool p) {
    asm volatile("cp.async.cg.shared.global [%0], [%1], 16, %2;"
                 :: "r"(dst), "l"(src), "r"(p ? 16u : 0u));
}
#define CP_COMMIT() asm volatile("cp.async.commit_group;")
#define CP_WAIT0()  asm volatile("cp.async.wait_group 0;" ::: "memory")
#define BAR_SYNC(id, cnt) asm volatile("bar.sync %0, %1;" :: "r"(id), "r"(cnt) : "memory")

__device__ __forceinline__ unsigned lds32(unsigned addr) {
    unsigned v;
    asm volatile("ld.shared.b32 %0, [%1];" : "=r"(v) : "r"(addr));
    return v;
}
__device__ __forceinline__ void mma_tf32(float c[4], const unsigned a[4],
                                         unsigned b0, unsigned b1) {
    asm volatile(
        "mma.sync.aligned.m16n8k8.row.col.f32.tf32.tf32.f32 "
        "{%0,%1,%2,%3}, {%4,%5,%6,%7}, {%8,%9}, {%0,%1,%2,%3};"
        : "+f"(c[0]), "+f"(c[1]), "+f"(c[2]), "+f"(c[3])
        : "r"(a[0]), "r"(a[1]), "r"(a[2]), "r"(a[3]), "r"(b0), "r"(b1));
}
__device__ __forceinline__ unsigned cvt_tf32u(unsigned v) {
    unsigned u;
    asm("cvt.rna.tf32.f32 %0, %1;" : "=r"(u) : "f"(__uint_as_float(v)));
    return u;
}
__device__ __forceinline__ float to_tf32(float v) {
    unsigned u;
    asm("cvt.rna.tf32.f32 %0, %1;" : "=r"(u) : "f"(v));
    return __uint_as_float(u);
}
__device__ __forceinline__ float hsig(float z) {
    return fminf(fmaxf(0.2f * z + 0.5f, 0.f), 1.f);
}

// perm v2: cout = g*64+fc -> n = (fc>>3)*32 + g*8 + (fc&7)
__host__ __device__ __forceinline__ int perm_n(int cout) {
    int g = cout >> 6, fc = cout & 63;
    return (fc >> 3) * 32 + g * 8 + (fc & 7);
}

// step smem: A[0:46080) (180 rows x 256B, swizzled),
// B per-pair: pair nw at SB_BASE + nw*16384, stages +0 / +8192 (total 64KB)
#define SB_BASE 46080
#define ST_SMEM (SB_BASE + 4 * 16384)        // 111616
// ic smem: A x-tile 561 rows x 128B = 71808; B stages 2 x 16384
#define ICB_BASE 71808
#define ICB_STAGE 16384
#define IC_SMEM (ICB_BASE + 2 * ICB_STAGE)   // 104576

// ---------------- prep ------------------------------------------------------
__global__ void prep_weights(const float* __restrict__ U,
                             const float* __restrict__ W,
                             const float* __restrict__ b) {
    int i = blockIdx.x * 256 + threadIdx.x;
    if (i < 9 * 64 * 256) {
        int tap = i / 16384, r = i % 16384, ci = r >> 8, cout = r & 255;
        g_ut[tap * 16384 + perm_n(cout) * 64 + ci] = to_tf32(U[i]);
    }
    if (i < 9 * 32 * 256) {
        int tap = i / 8192, r = i % 8192, ci = r >> 8, cout = r & 255;
        g_wt[tap * 8192 + perm_n(cout) * 32 + ci] = to_tf32(W[i]);
    }
    if (i < 256) g_bperm[perm_n(i)] = b[i];
}

// ---------------- input conv (unchanged from R10) ---------------------------
__device__ __forceinline__ void fill_icb(unsigned dst, int tap, int nh, int tid) {
    const float* wt = g_wt + tap * 8192 + nh * 128 * 32;
    for (int i = tid; i < 1024; i += 256) {
        int n = i >> 3, cc = i & 7;
        cp16p(dst + n * 128 + ((cc ^ (n & 7)) << 4), wt + n * 32 + cc * 4, true);
    }
    CP_COMMIT();
}

__global__ __launch_bounds__(256, 2) void ic_mma_kernel(
    const float* __restrict__ x, float* __restrict__ xz)
{
    extern __shared__ __align__(1024) char smem[];
    unsigned sb = smem_u32(smem);
    const int tid = threadIdx.x, lane = tid & 31, wid = tid >> 5;
    const int mw = wid >> 2, nw = wid & 3;
    const int r = lane >> 2, cq = lane & 3;
    const int mt = blockIdx.x;
    const int img = blockIdx.y >> 1, nh = blockIdx.y & 1;
    const int oh0 = (mt >> 2) * 8, ow0 = (mt & 3) * 16;
    const int ih0 = 2 * oh0, iw0 = 2 * ow0;

    // A fill: 561 tile-rows x 8 chunks, raw fp32 x, zero-fill OOB
    for (int i = tid; i < 4488; i += 256) {
        int row = i >> 3, cc = i & 7;
        int trow = row / 33, tcol = row - trow * 33;
        int ih = ih0 + trow, iw = iw0 + tcol;
        bool ok = (ih < 128 && iw < 128);
        const float* s = x +
            (((size_t)img * 128 + (ok ? ih : 0)) * 128 + (ok ? iw : 0)) * 32 + cc * 4;
        cp16p(sb + row * 128 + ((cc ^ ((row >> 1) & 7)) << 4), s, ok);
    }
    fill_icb(sb + ICB_BASE, 0, nh, tid);     // commits A + B0 together

    unsigned nbase[4];
#pragma unroll
    for (int nf = 0; nf < 4; nf++)
        nbase[nf] = (unsigned)((nw * 32 + nf * 8 + r) * 128 + cq * 4);

    float acc[4][4][4];
#pragma unroll
    for (int a = 0; a < 4; a++)
#pragma unroll
        for (int b = 0; b < 4; b++)
#pragma unroll
            for (int c = 0; c < 4; c++) acc[a][b][c] = 0.f;

    for (int tap = 0; tap < 9; tap++) {
        CP_WAIT0();
        __syncthreads();
        if (tap < 8)
            fill_icb(sb + ICB_BASE + ((tap + 1) & 1) * ICB_STAGE, tap + 1, nh, tid);
        const int kh = tap / 3, kw = tap - kh * 3;
        unsigned Bst = sb + ICB_BASE + (tap & 1) * ICB_STAGE;

        unsigned abase[4];
        int akey[4];
#pragma unroll
        for (int mf = 0; mf < 4; mf++) {
            int row0 = (2 * (mw * 4 + mf) + kh) * 33 + (2 * r + kw);
            abase[mf] = sb + (unsigned)(row0 * 128 + cq * 4);
            akey[mf] = (row0 >> 1) & 7;      // same key for row0+16
        }

#pragma unroll
        for (int k = 0; k < 4; k++) {
            unsigned av[4][4], bv[4][2];
#pragma unroll
            for (int mf = 0; mf < 4; mf++) {
                unsigned o0 = (unsigned)(((2 * k) ^ akey[mf]) << 4);
                av[mf][0] = cvt_tf32u(lds32(abase[mf] + o0));
                av[mf][1] = cvt_tf32u(lds32(abase[mf] + o0 + 2048));  // sc +8
                av[mf][2] = cvt_tf32u(lds32(abase[mf] + (o0 ^ 16)));
                av[mf][3] = cvt_tf32u(lds32(abase[mf] + (o0 ^ 16) + 2048));
            }
            {
                unsigned o0 = (unsigned)(((2 * k) ^ r) << 4);   // B row&7 == r
#pragma unroll
                for (int nf = 0; nf < 4; nf++) {
                    bv[nf][0] = lds32(Bst + nbase[nf] + o0);
                    bv[nf][1] = lds32(Bst + nbase[nf] + (o0 ^ 16));
                }
            }
#pragma unroll
            for (int mf = 0; mf < 4; mf++)
#pragma unroll
                for (int nf = 0; nf < 4; nf++)
                    mma_tf32(acc[mf][nf], av[mf], bv[nf][0], bv[nf][1]);
        }
    }

    // epilogue: +bias(perm), write fragment blob (R10 layout)
    float2 bvq[4];
#pragma unroll
    for (int nf = 0; nf < 4; nf++)
        bvq[nf] = *(const float2*)(g_bperm + nh * 128 + nw * 32 + nf * 8 + 2 * cq);
    float* blob = xz + ((((size_t)img * 32 + mt) * 2 + nh) * 8 + wid) * 2048 + lane;
#pragma unroll
    for (int mf = 0; mf < 4; mf++)
#pragma unroll
        for (int nf = 0; nf < 4; nf++)
#pragma unroll
            for (int rg = 0; rg < 4; rg++)
                blob[((mf * 4 + nf) * 4 + rg) * 32] =
                    acc[mf][nf][rg] + ((rg & 1) ? bvq[nf].y : bvq[nf].x);
}

// ---------------- LSTM step: per-pair B staging, named barriers -------------
// Producer (mw==0) fills its pair's 32-row B slice (8KB) per tap, own cp group.
__device__ __forceinline__ void fill_b_pair(unsigned dst, int tap, int nh,
                                            int nw, int lane) {
    const float* ut = g_ut + tap * 16384 + (nh * 128 + nw * 32) * 64;
#pragma unroll
    for (int i = lane; i < 512; i += 32) {
        int n = i >> 4, cc = i & 15;     // n 0..31, cc 0..15
        cp16p(dst + n * 256 + ((cc ^ (n & 7)) << 4), ut + n * 64 + cc * 4, true);
    }
    CP_COMMIT();
}

__global__ __launch_bounds__(256, 2) void lstm_step_mma(
    const float* __restrict__ hin, float* __restrict__ hout,
    float* __restrict__ cbuf, const float* __restrict__ xz,
    const float* __restrict__ gamma, const float* __restrict__ beta,
    const float* __restrict__ mmean, const float* __restrict__ mvar,
    float* __restrict__ out, int t)
{
    extern __shared__ __align__(1024) char smem[];
    unsigned sb = smem_u32(smem);
    const int tid = threadIdx.x, lane = tid & 31, wid = tid >> 5;
    const int mw = wid >> 2, nw = wid & 3;
    const int r = lane >> 2, cq = lane & 3;
    const int mt = blockIdx.x;
    const int bb = blockIdx.y >> 1, nh = blockIdx.y & 1;
    const int oh0 = (mt >> 2) * 8, ow0 = (mt & 3) * 16;

    const unsigned pairB = sb + SB_BASE + (unsigned)(nw * 16384);

    // A: halo'd h tile 10x18 spatial rows x 256B (64ch fp32), swizzled; once
    for (int i = tid; i < 2880; i += 256) {
        int row = i >> 4, cc = i & 15;
        int sr = row / 18, sc = row - sr * 18;
        int ih = oh0 - 1 + sr, iw = ow0 - 1 + sc;
        bool ok = (ih >= 0 && ih < H2 && iw >= 0 && iw < W2);
        const float* s = hin +
            (((size_t)bb * H2 + (ok ? ih : 0)) * W2 + (ok ? iw : 0)) * FCH + cc * 4;
        cp16p(sb + row * 256 + ((cc ^ (row & 7)) << 4), s, ok);
    }
    if (mw == 0) fill_b_pair(pairB, 0, nh, nw, lane);
    CP_COMMIT();
    CP_WAIT0();
    __syncthreads();                          // publish A + all pairs' B0

    unsigned nbase[4];
#pragma unroll
    for (int nf = 0; nf < 4; nf++)
        nbase[nf] = (unsigned)((nf * 8 + r) * 256 + cq * 4);   // slice-local

    float acc[4][4][4];
#pragma unroll
    for (int a = 0; a < 4; a++)
#pragma unroll
        for (int b = 0; b < 4; b++)
#pragma unroll
            for (int c = 0; c < 4; c++) acc[a][b][c] = 0.f;

    for (int tap = 0; tap < 9; tap++) {
        if (mw == 0 && tap < 8)
            fill_b_pair(pairB + (unsigned)(((tap + 1) & 1) * 8192),
                        tap + 1, nh, nw, lane);
        const int kh = tap / 3, kw = tap - kh * 3;
        unsigned Bst = pairB + (unsigned)((tap & 1) * 8192);

        unsigned abase[4];
        int ar7[4];
#pragma unroll
        for (int mf = 0; mf < 4; mf++) {
            int row0 = (mw * 4 + mf + kh) * 18 + r + kw;
            abase[mf] = sb + (unsigned)(row0 * 256 + cq * 4);
            ar7[mf] = row0 & 7;
        }

#pragma unroll
        for (int k = 0; k < 8; k++) {
            unsigned av[4][4], bv[4][2];
#pragma unroll
            for (int mf = 0; mf < 4; mf++) {
                unsigned o0 = (unsigned)(((2 * k) ^ ar7[mf]) << 4);
                av[mf][0] = lds32(abase[mf] + o0);
                av[mf][1] = lds32(abase[mf] + o0 + 2048);       // ow +8
                av[mf][2] = lds32(abase[mf] + (o0 ^ 16));
                av[mf][3] = lds32(abase[mf] + (o0 ^ 16) + 2048);
            }
            {
                unsigned o0 = (unsigned)(((2 * k) ^ r) << 4);   // slice row&7 == r
#pragma unroll
                for (int nf = 0; nf < 4; nf++) {
                    bv[nf][0] = lds32(Bst + nbase[nf] + o0);
                    bv[nf][1] = lds32(Bst + nbase[nf] + (o0 ^ 16));
                }
            }
#pragma unroll
            for (int mf = 0; mf < 4; mf++)
#pragma unroll
                for (int nf = 0; nf < 4; nf++)
                    mma_tf32(acc[mf][nf], av[mf], bv[nf][0], bv[nf][1]);
        }

        if (tap < 8) {
            if (mw == 0) CP_WAIT0();          // pair's fill(tap+1) landed
            BAR_SYNC(nw + 1, 64);             // publish to consumer; reuse ok
        }
    }

    // add xz (bias folded), R10 blob layout
    const float* blob = xz +
        ((((size_t)(bb * TSTEPS + t) * 32 + mt) * 2 + nh) * 8 + wid) * 2048 + lane;
#pragma unroll
    for (int mf = 0; mf < 4; mf++)
#pragma unroll
        for (int nf = 0; nf < 4; nf++)
#pragma unroll
            for (int rg = 0; rg < 4; rg++)
                acc[mf][nf][rg] += blob[((mf * 4 + nf) * 4 + rg) * 32];

    // gates in-register: nf = gate; lane fc pair fc0, fc0+1
    const int fc0 = (nh * 4 + nw) * 8 + 2 * cq;
    float2 gm = *(const float2*)(gamma + fc0);
    float2 bt = *(const float2*)(beta + fc0);
    float2 mu = *(const float2*)(mmean + fc0);
    float2 vr = *(const float2*)(mvar + fc0);
    float sc0 = gm.x * rsqrtf(vr.x + 1e-3f);
    float sc1 = gm.y * rsqrtf(vr.y + 1e-3f);

#pragma unroll
    for (int mf = 0; mf < 4; mf++) {
        int oh = oh0 + mw * 4 + mf;
#pragma unroll
        for (int rh = 0; rh < 2; rh++) {
            int ow = ow0 + r + 8 * rh;
            size_t sidx = (((size_t)bb * H2 + oh) * W2 + ow) * FCH + fc0;
            float2 cc2 = *(const float2*)(cbuf + sidx);
            float cn[2], hn[2], ov[2];
#pragma unroll
            for (int q = 0; q < 2; q++) {
                float zi = acc[mf][0][2 * rh + q];
                float zf = acc[mf][1][2 * rh + q];
                float zg = acc[mf][2][2 * rh + q];
                float zo = acc[mf][3][2 * rh + q];
                float co = q ? cc2.y : cc2.x;
                float c2 = hsig(zf) * co + hsig(zi) * tanhf(zg);
                hn[q] = hsig(zo) * tanhf(c2);
                cn[q] = c2;
                float s = q ? sc1 : sc0;
                ov[q] = (hn[q] - (q ? mu.y : mu.x)) * s + (q ? bt.y : bt.x);
            }
            *(float2*)(cbuf + sidx) = make_float2(cn[0], cn[1]);
            *(float2*)(hout + sidx) = make_float2(to_tf32(hn[0]), to_tf32(hn[1]));
            *(float2*)(out + ((((size_t)bb * TSTEPS + t) * H2 + oh) * W2 + ow) * FCH + fc0)
                = make_float2(ov[0], ov[1]);
        }
    }
}

// ---------------------------------------------------------------------------
extern "C" void kernel_launch(void* const* d_in, const int* in_sizes, int n_in,
                              void* d_out, int out_size)
{
    const float* x     = (const float*)d_in[0];
    const float* W     = (const float*)d_in[1];
    const float* U     = (const float*)d_in[2];
    const float* b     = (const float*)d_in[3];
    const float* gamma = (const float*)d_in[4];
    const float* beta  = (const float*)d_in[5];
    const float* mm    = (const float*)d_in[6];
    const float* mv    = (const float*)d_in[7];
    float* out = (float*)d_out;

    float *xz, *cbuf, *hbuf;
    cudaGetSymbolAddress((void**)&xz, g_xz);
    cudaGetSymbolAddress((void**)&cbuf, g_c);
    cudaGetSymbolAddress((void**)&hbuf, g_ht);
    const size_t hsz = (size_t)BATCH * H2 * W2 * FCH;

    cudaFuncSetAttribute(ic_mma_kernel,
                         cudaFuncAttributeMaxDynamicSharedMemorySize, IC_SMEM);
    cudaFuncSetAttribute(lstm_step_mma,
                         cudaFuncAttributeMaxDynamicSharedMemorySize, ST_SMEM);

    cudaMemsetAsync(hbuf, 0, hsz * sizeof(float));
    cudaMemsetAsync(cbuf, 0, hsz * sizeof(float));

    prep_weights<<<576, 256>>>(U, W, b);
    ic_mma_kernel<<<dim3(32, 128), 256, IC_SMEM>>>(x, xz);

    for (int t = 0; t < TSTEPS; t++) {
        int rd = t & 1, wr = (t + 1) & 1;
        lstm_step_mma<<<dim3(32, 8), 256, ST_SMEM>>>(
            hbuf + rd * hsz, hbuf + wr * hsz,
            cbuf, xz, gamma, beta, mm, mv, out, t);
    }
}

// round 14
// speedup vs baseline: 1.5395x; 1.0312x over previous
#include <cuda_runtime.h>
#include <cuda_bf16.h>

// ---------------------------------------------------------------------------
// ConvLSTM via mma.sync tf32 single-pass, fp32 accum. Round 14.
// R13 base (proven 839.6us); one change: L2-prefetch of each step-CTA's xz
// fragment blob at kernel start so the epilogue reads hit L2 instead of
// issuing a cold 16.8MB/step DRAM burst after the last MMA.
// ---------------------------------------------------------------------------

#define H2 64
#define W2 64
#define FCH 64
#define BATCH 4
#define TSTEPS 16
#define NIMG 64

// xz blob: [img][mt32][nh2][warp8][frag64][lane32] floats
__device__ float g_xz[(size_t)NIMG * 32 * 2 * 8 * 64 * 32];          // 268 MB
__device__ float g_ut[9 * 256 * 64];     // [tap][n_perm][ci], tf32-rounded
__device__ float g_wt[9 * 256 * 32];     // [tap][n_perm][ci]
__device__ float g_bperm[256];
__device__ float g_ht[2][(size_t)BATCH * H2 * W2 * FCH];             // 2 x 4 MB
__device__ float g_c[(size_t)BATCH * H2 * W2 * FCH];

// ---------------- helpers ---------------------------------------------------
__device__ __forceinline__ unsigned smem_u32(const void* p) {
    return (unsigned)__cvta_generic_to_shared(p);
}
__device__ __forceinline__ void cp16p(unsigned dst, const void* src, bool p) {
    asm volatile("cp.async.cg.shared.global [%0], [%1], 16, %2;"
                 :: "r"(dst), "l"(src), "r"(p ? 16u : 0u));
}
#define CP_COMMIT() asm volatile("cp.async.commit_group;")
#define CP_WAIT0()  asm volatile("cp.async.wait_group 0;" ::: "memory")
#define BAR_SYNC(id, cnt) asm volatile("bar.sync %0, %1;" :: "r"(id), "r"(cnt) : "memory")

__device__ __forceinline__ void l2_prefetch(const void* p) {
    asm volatile("prefetch.global.L2 [%0];" :: "l"(p));
}
__device__ __forceinline__ unsigned lds32(unsigned addr) {
    unsigned v;
    asm volatile("ld.shared.b32 %0, [%1];" : "=r"(v) : "r"(addr));
    return v;
}
__device__ __forceinline__ void mma_tf32(float c[4], const unsigned a[4],
                                         unsigned b0, unsigned b1) {
    asm volatile(
        "mma.sync.aligned.m16n8k8.row.col.f32.tf32.tf32.f32 "
        "{%0,%1,%2,%3}, {%4,%5,%6,%7}, {%8,%9}, {%0,%1,%2,%3};"
        : "+f"(c[0]), "+f"(c[1]), "+f"(c[2]), "+f"(c[3])
        : "r"(a[0]), "r"(a[1]), "r"(a[2]), "r"(a[3]), "r"(b0), "r"(b1));
}
__device__ __forceinline__ unsigned cvt_tf32u(unsigned v) {
    unsigned u;
    asm("cvt.rna.tf32.f32 %0, %1;" : "=r"(u) : "f"(__uint_as_float(v)));
    return u;
}
__device__ __forceinline__ float to_tf32(float v) {
    unsigned u;
    asm("cvt.rna.tf32.f32 %0, %1;" : "=r"(u) : "f"(v));
    return __uint_as_float(u);
}
__device__ __forceinline__ float hsig(float z) {
    return fminf(fmaxf(0.2f * z + 0.5f, 0.f), 1.f);
}

// perm v2: cout = g*64+fc -> n = (fc>>3)*32 + g*8 + (fc&7)
__host__ __device__ __forceinline__ int perm_n(int cout) {
    int g = cout >> 6, fc = cout & 63;
    return (fc >> 3) * 32 + g * 8 + (fc & 7);
}

// step smem: A[0:46080) (180 rows x 256B, swizzled),
// B per-pair: pair nw at SB_BASE + nw*16384, stages +0 / +8192 (total 64KB)
#define SB_BASE 46080
#define ST_SMEM (SB_BASE + 4 * 16384)        // 111616
// ic smem: A x-tile 561 rows x 128B = 71808; B stages 2 x 16384
#define ICB_BASE 71808
#define ICB_STAGE 16384
#define IC_SMEM (ICB_BASE + 2 * ICB_STAGE)   // 104576

// ---------------- prep ------------------------------------------------------
__global__ void prep_weights(const float* __restrict__ U,
                             const float* __restrict__ W,
                             const float* __restrict__ b) {
    int i = blockIdx.x * 256 + threadIdx.x;
    if (i < 9 * 64 * 256) {
        int tap = i / 16384, r = i % 16384, ci = r >> 8, cout = r & 255;
        g_ut[tap * 16384 + perm_n(cout) * 64 + ci] = to_tf32(U[i]);
    }
    if (i < 9 * 32 * 256) {
        int tap = i / 8192, r = i % 8192, ci = r >> 8, cout = r & 255;
        g_wt[tap * 8192 + perm_n(cout) * 32 + ci] = to_tf32(W[i]);
    }
    if (i < 256) g_bperm[perm_n(i)] = b[i];
}

// ---------------- input conv (unchanged from R13) ---------------------------
__device__ __forceinline__ void fill_icb(unsigned dst, int tap, int nh, int tid) {
    const float* wt = g_wt + tap * 8192 + nh * 128 * 32;
    for (int i = tid; i < 1024; i += 256) {
        int n = i >> 3, cc = i & 7;
        cp16p(dst + n * 128 + ((cc ^ (n & 7)) << 4), wt + n * 32 + cc * 4, true);
    }
    CP_COMMIT();
}

__global__ __launch_bounds__(256, 2) void ic_mma_kernel(
    const float* __restrict__ x, float* __restrict__ xz)
{
    extern __shared__ __align__(1024) char smem[];
    unsigned sb = smem_u32(smem);
    const int tid = threadIdx.x, lane = tid & 31, wid = tid >> 5;
    const int mw = wid >> 2, nw = wid & 3;
    const int r = lane >> 2, cq = lane & 3;
    const int mt = blockIdx.x;
    const int img = blockIdx.y >> 1, nh = blockIdx.y & 1;
    const int oh0 = (mt >> 2) * 8, ow0 = (mt & 3) * 16;
    const int ih0 = 2 * oh0, iw0 = 2 * ow0;

    // A fill: 561 tile-rows x 8 chunks, raw fp32 x, zero-fill OOB
    for (int i = tid; i < 4488; i += 256) {
        int row = i >> 3, cc = i & 7;
        int trow = row / 33, tcol = row - trow * 33;
        int ih = ih0 + trow, iw = iw0 + tcol;
        bool ok = (ih < 128 && iw < 128);
        const float* s = x +
            (((size_t)img * 128 + (ok ? ih : 0)) * 128 + (ok ? iw : 0)) * 32 + cc * 4;
        cp16p(sb + row * 128 + ((cc ^ ((row >> 1) & 7)) << 4), s, ok);
    }
    fill_icb(sb + ICB_BASE, 0, nh, tid);     // commits A + B0 together

    unsigned nbase[4];
#pragma unroll
    for (int nf = 0; nf < 4; nf++)
        nbase[nf] = (unsigned)((nw * 32 + nf * 8 + r) * 128 + cq * 4);

    float acc[4][4][4];
#pragma unroll
    for (int a = 0; a < 4; a++)
#pragma unroll
        for (int b = 0; b < 4; b++)
#pragma unroll
            for (int c = 0; c < 4; c++) acc[a][b][c] = 0.f;

    for (int tap = 0; tap < 9; tap++) {
        CP_WAIT0();
        __syncthreads();
        if (tap < 8)
            fill_icb(sb + ICB_BASE + ((tap + 1) & 1) * ICB_STAGE, tap + 1, nh, tid);
        const int kh = tap / 3, kw = tap - kh * 3;
        unsigned Bst = sb + ICB_BASE + (tap & 1) * ICB_STAGE;

        unsigned abase[4];
        int akey[4];
#pragma unroll
        for (int mf = 0; mf < 4; mf++) {
            int row0 = (2 * (mw * 4 + mf) + kh) * 33 + (2 * r + kw);
            abase[mf] = sb + (unsigned)(row0 * 128 + cq * 4);
            akey[mf] = (row0 >> 1) & 7;      // same key for row0+16
        }

#pragma unroll
        for (int k = 0; k < 4; k++) {
            unsigned av[4][4], bv[4][2];
#pragma unroll
            for (int mf = 0; mf < 4; mf++) {
                unsigned o0 = (unsigned)(((2 * k) ^ akey[mf]) << 4);
                av[mf][0] = cvt_tf32u(lds32(abase[mf] + o0));
                av[mf][1] = cvt_tf32u(lds32(abase[mf] + o0 + 2048));  // sc +8
                av[mf][2] = cvt_tf32u(lds32(abase[mf] + (o0 ^ 16)));
                av[mf][3] = cvt_tf32u(lds32(abase[mf] + (o0 ^ 16) + 2048));
            }
            {
                unsigned o0 = (unsigned)(((2 * k) ^ r) << 4);   // B row&7 == r
#pragma unroll
                for (int nf = 0; nf < 4; nf++) {
                    bv[nf][0] = lds32(Bst + nbase[nf] + o0);
                    bv[nf][1] = lds32(Bst + nbase[nf] + (o0 ^ 16));
                }
            }
#pragma unroll
            for (int mf = 0; mf < 4; mf++)
#pragma unroll
                for (int nf = 0; nf < 4; nf++)
                    mma_tf32(acc[mf][nf], av[mf], bv[nf][0], bv[nf][1]);
        }
    }

    // epilogue: +bias(perm), write fragment blob (R10 layout)
    float2 bvq[4];
#pragma unroll
    for (int nf = 0; nf < 4; nf++)
        bvq[nf] = *(const float2*)(g_bperm + nh * 128 + nw * 32 + nf * 8 + 2 * cq);
    float* blob = xz + ((((size_t)img * 32 + mt) * 2 + nh) * 8 + wid) * 2048 + lane;
#pragma unroll
    for (int mf = 0; mf < 4; mf++)
#pragma unroll
        for (int nf = 0; nf < 4; nf++)
#pragma unroll
            for (int rg = 0; rg < 4; rg++)
                blob[((mf * 4 + nf) * 4 + rg) * 32] =
                    acc[mf][nf][rg] + ((rg & 1) ? bvq[nf].y : bvq[nf].x);
}

// ---------------- LSTM step: per-pair B staging + xz L2 prefetch ------------
__device__ __forceinline__ void fill_b_pair(unsigned dst, int tap, int nh,
                                            int nw, int lane) {
    const float* ut = g_ut + tap * 16384 + (nh * 128 + nw * 32) * 64;
#pragma unroll
    for (int i = lane; i < 512; i += 32) {
        int n = i >> 4, cc = i & 15;     // n 0..31, cc 0..15
        cp16p(dst + n * 256 + ((cc ^ (n & 7)) << 4), ut + n * 64 + cc * 4, true);
    }
    CP_COMMIT();
}

__global__ __launch_bounds__(256, 2) void lstm_step_mma(
    const float* __restrict__ hin, float* __restrict__ hout,
    float* __restrict__ cbuf, const float* __restrict__ xz,
    const float* __restrict__ gamma, const float* __restrict__ beta,
    const float* __restrict__ mmean, const float* __restrict__ mvar,
    float* __restrict__ out, int t)
{
    extern __shared__ __align__(1024) char smem[];
    unsigned sb = smem_u32(smem);
    const int tid = threadIdx.x, lane = tid & 31, wid = tid >> 5;
    const int mw = wid >> 2, nw = wid & 3;
    const int r = lane >> 2, cq = lane & 3;
    const int mt = blockIdx.x;
    const int bb = blockIdx.y >> 1, nh = blockIdx.y & 1;
    const int oh0 = (mt >> 2) * 8, ow0 = (mt & 3) * 16;

    const unsigned pairB = sb + SB_BASE + (unsigned)(nw * 16384);

    // L2-prefetch this CTA's 64KB xz blob (consumed only in the epilogue):
    // 512 x 128B lines, 2 per thread, issued before anything waits.
    {
        const float* pf = xz +
            ((((size_t)(bb * TSTEPS + t) * 32 + mt) * 2 + nh) * 8) * 2048;
        l2_prefetch(pf + tid * 32);
        l2_prefetch(pf + (tid + 256) * 32);
    }

    // A: halo'd h tile 10x18 spatial rows x 256B (64ch fp32), swizzled; once
    for (int i = tid; i < 2880; i += 256) {
        int row = i >> 4, cc = i & 15;
        int sr = row / 18, sc = row - sr * 18;
        int ih = oh0 - 1 + sr, iw = ow0 - 1 + sc;
        bool ok = (ih >= 0 && ih < H2 && iw >= 0 && iw < W2);
        const float* s = hin +
            (((size_t)bb * H2 + (ok ? ih : 0)) * W2 + (ok ? iw : 0)) * FCH + cc * 4;
        cp16p(sb + row * 256 + ((cc ^ (row & 7)) << 4), s, ok);
    }
    if (mw == 0) fill_b_pair(pairB, 0, nh, nw, lane);
    CP_COMMIT();
    CP_WAIT0();
    __syncthreads();                          // publish A + all pairs' B0

    unsigned nbase[4];
#pragma unroll
    for (int nf = 0; nf < 4; nf++)
        nbase[nf] = (unsigned)((nf * 8 + r) * 256 + cq * 4);   // slice-local

    float acc[4][4][4];
#pragma unroll
    for (int a = 0; a < 4; a++)
#pragma unroll
        for (int b = 0; b < 4; b++)
#pragma unroll
            for (int c = 0; c < 4; c++) acc[a][b][c] = 0.f;

    for (int tap = 0; tap < 9; tap++) {
        if (mw == 0 && tap < 8)
            fill_b_pair(pairB + (unsigned)(((tap + 1) & 1) * 8192),
                        tap + 1, nh, nw, lane);
        const int kh = tap / 3, kw = tap - kh * 3;
        unsigned Bst = pairB + (unsigned)((tap & 1) * 8192);

        unsigned abase[4];
        int ar7[4];
#pragma unroll
        for (int mf = 0; mf < 4; mf++) {
            int row0 = (mw * 4 + mf + kh) * 18 + r + kw;
            abase[mf] = sb + (unsigned)(row0 * 256 + cq * 4);
            ar7[mf] = row0 & 7;
        }

#pragma unroll
        for (int k = 0; k < 8; k++) {
            unsigned av[4][4], bv[4][2];
#pragma unroll
            for (int mf = 0; mf < 4; mf++) {
                unsigned o0 = (unsigned)(((2 * k) ^ ar7[mf]) << 4);
                av[mf][0] = lds32(abase[mf] + o0);
                av[mf][1] = lds32(abase[mf] + o0 + 2048);       // ow +8
                av[mf][2] = lds32(abase[mf] + (o0 ^ 16));
                av[mf][3] = lds32(abase[mf] + (o0 ^ 16) + 2048);
            }
            {
                unsigned o0 = (unsigned)(((2 * k) ^ r) << 4);   // slice row&7 == r
#pragma unroll
                for (int nf = 0; nf < 4; nf++) {
                    bv[nf][0] = lds32(Bst + nbase[nf] + o0);
                    bv[nf][1] = lds32(Bst + nbase[nf] + (o0 ^ 16));
                }
            }
#pragma unroll
            for (int mf = 0; mf < 4; mf++)
#pragma unroll
                for (int nf = 0; nf < 4; nf++)
                    mma_tf32(acc[mf][nf], av[mf], bv[nf][0], bv[nf][1]);
        }

        if (tap < 8) {
            if (mw == 0) CP_WAIT0();          // pair's fill(tap+1) landed
            BAR_SYNC(nw + 1, 64);             // publish to consumer; reuse ok
        }
    }

    // add xz (bias folded), R10 blob layout — L2-hot from the prefetch
    const float* blob = xz +
        ((((size_t)(bb * TSTEPS + t) * 32 + mt) * 2 + nh) * 8 + wid) * 2048 + lane;
#pragma unroll
    for (int mf = 0; mf < 4; mf++)
#pragma unroll
        for (int nf = 0; nf < 4; nf++)
#pragma unroll
            for (int rg = 0; rg < 4; rg++)
                acc[mf][nf][rg] += blob[((mf * 4 + nf) * 4 + rg) * 32];

    // gates in-register: nf = gate; lane fc pair fc0, fc0+1
    const int fc0 = (nh * 4 + nw) * 8 + 2 * cq;
    float2 gm = *(const float2*)(gamma + fc0);
    float2 bt = *(const float2*)(beta + fc0);
    float2 mu = *(const float2*)(mmean + fc0);
    float2 vr = *(const float2*)(mvar + fc0);
    float sc0 = gm.x * rsqrtf(vr.x + 1e-3f);
    float sc1 = gm.y * rsqrtf(vr.y + 1e-3f);

#pragma unroll
    for (int mf = 0; mf < 4; mf++) {
        int oh = oh0 + mw * 4 + mf;
#pragma unroll
        for (int rh = 0; rh < 2; rh++) {
            int ow = ow0 + r + 8 * rh;
            size_t sidx = (((size_t)bb * H2 + oh) * W2 + ow) * FCH + fc0;
            float2 cc2 = *(const float2*)(cbuf + sidx);
            float cn[2], hn[2], ov[2];
#pragma unroll
            for (int q = 0; q < 2; q++) {
                float zi = acc[mf][0][2 * rh + q];
                float zf = acc[mf][1][2 * rh + q];
                float zg = acc[mf][2][2 * rh + q];
                float zo = acc[mf][3][2 * rh + q];
                float co = q ? cc2.y : cc2.x;
                float c2 = hsig(zf) * co + hsig(zi) * tanhf(zg);
                hn[q] = hsig(zo) * tanhf(c2);
                cn[q] = c2;
                float s = q ? sc1 : sc0;
                ov[q] = (hn[q] - (q ? mu.y : mu.x)) * s + (q ? bt.y : bt.x);
            }
            *(float2*)(cbuf + sidx) = make_float2(cn[0], cn[1]);
            *(float2*)(hout + sidx) = make_float2(to_tf32(hn[0]), to_tf32(hn[1]));
            *(float2*)(out + ((((size_t)bb * TSTEPS + t) * H2 + oh) * W2 + ow) * FCH + fc0)
                = make_float2(ov[0], ov[1]);
        }
    }
}

// ---------------------------------------------------------------------------
extern "C" void kernel_launch(void* const* d_in, const int* in_sizes, int n_in,
                              void* d_out, int out_size)
{
    const float* x     = (const float*)d_in[0];
    const float* W     = (const float*)d_in[1];
    const float* U     = (const float*)d_in[2];
    const float* b     = (const float*)d_in[3];
    const float* gamma = (const float*)d_in[4];
    const float* beta  = (const float*)d_in[5];
    const float* mm    = (const float*)d_in[6];
    const float* mv    = (const float*)d_in[7];
    float* out = (float*)d_out;

    float *xz, *cbuf, *hbuf;
    cudaGetSymbolAddress((void**)&xz, g_xz);
    cudaGetSymbolAddress((void**)&cbuf, g_c);
    cudaGetSymbolAddress((void**)&hbuf, g_ht);
    const size_t hsz = (size_t)BATCH * H2 * W2 * FCH;

    cudaFuncSetAttribute(ic_mma_kernel,
                         cudaFuncAttributeMaxDynamicSharedMemorySize, IC_SMEM);
    cudaFuncSetAttribute(lstm_step_mma,
                         cudaFuncAttributeMaxDynamicSharedMemorySize, ST_SMEM);

    cudaMemsetAsync(hbuf, 0, hsz * sizeof(float));
    cudaMemsetAsync(cbuf, 0, hsz * sizeof(float));

    prep_weights<<<576, 256>>>(U, W, b);
    ic_mma_kernel<<<dim3(32, 128), 256, IC_SMEM>>>(x, xz);

    for (int t = 0; t < TSTEPS; t++) {
        int rd = t & 1, wr = (t + 1) & 1;
        lstm_step_mma<<<dim3(32, 8), 256, ST_SMEM>>>(
            hbuf + rd * hsz, hbuf + wr * hsz,
            cbuf, xz, gamma, beta, mm, mv, out, t);
    }
}

// round 16
// speedup vs baseline: 1.5981x; 1.0381x over previous
#include <cuda_runtime.h>
#include <cuda_fp16.h>

// ---------------------------------------------------------------------------
// ConvLSTM via mma.sync tf32 single-pass, fp32 accum. Round 15.
// R14 base; changes: (1) xz fragment blob stored as fp16 half2 pairs
// (134MB, halves blob traffic), (2) ic kernel uses per-pair producer-warp
// B staging + named barriers (pattern validated in step kernel R13).
// ---------------------------------------------------------------------------

#define H2 64
#define W2 64
#define FCH 64
#define BATCH 4
#define TSTEPS 16
#define NIMG 64

// xz blob: [img][mt32][nh2][warp8][pair32][lane32] half2-in-uint (134 MB)
__device__ unsigned g_xz[(size_t)NIMG * 32 * 2 * 8 * 32 * 32];
__device__ float g_ut[9 * 256 * 64];     // [tap][n_perm][ci], tf32-rounded
__device__ float g_wt[9 * 256 * 32];     // [tap][n_perm][ci]
__device__ float g_bperm[256];
__device__ float g_ht[2][(size_t)BATCH * H2 * W2 * FCH];             // 2 x 4 MB
__device__ float g_c[(size_t)BATCH * H2 * W2 * FCH];

// ---------------- helpers ---------------------------------------------------
__device__ __forceinline__ unsigned smem_u32(const void* p) {
    return (unsigned)__cvta_generic_to_shared(p);
}
__device__ __forceinline__ void cp16p(unsigned dst, const void* src, bool p) {
    asm volatile("cp.async.cg.shared.global [%0], [%1], 16, %2;"
                 :: "r"(dst), "l"(src), "r"(p ? 16u : 0u));
}
#define CP_COMMIT() asm volatile("cp.async.commit_group;")
#define CP_WAIT0()  asm volatile("cp.async.wait_group 0;" ::: "memory")
#define BAR_SYNC(id, cnt) asm volatile("bar.sync %0, %1;" :: "r"(id), "r"(cnt) : "memory")

__device__ __forceinline__ void l2_prefetch(const void* p) {
    asm volatile("prefetch.global.L2 [%0];" :: "l"(p));
}
__device__ __forceinline__ unsigned lds32(unsigned addr) {
    unsigned v;
    asm volatile("ld.shared.b32 %0, [%1];" : "=r"(v) : "r"(addr));
    return v;
}
__device__ __forceinline__ void mma_tf32(float c[4], const unsigned a[4],
                                         unsigned b0, unsigned b1) {
    asm volatile(
        "mma.sync.aligned.m16n8k8.row.col.f32.tf32.tf32.f32 "
        "{%0,%1,%2,%3}, {%4,%5,%6,%7}, {%8,%9}, {%0,%1,%2,%3};"
        : "+f"(c[0]), "+f"(c[1]), "+f"(c[2]), "+f"(c[3])
        : "r"(a[0]), "r"(a[1]), "r"(a[2]), "r"(a[3]), "r"(b0), "r"(b1));
}
__device__ __forceinline__ unsigned cvt_tf32u(unsigned v) {
    unsigned u;
    asm("cvt.rna.tf32.f32 %0, %1;" : "=r"(u) : "f"(__uint_as_float(v)));
    return u;
}
__device__ __forceinline__ float to_tf32(float v) {
    unsigned u;
    asm("cvt.rna.tf32.f32 %0, %1;" : "=r"(u) : "f"(v));
    return __uint_as_float(u);
}
__device__ __forceinline__ float hsig(float z) {
    return fminf(fmaxf(0.2f * z + 0.5f, 0.f), 1.f);
}

// perm v2: cout = g*64+fc -> n = (fc>>3)*32 + g*8 + (fc&7)
__host__ __device__ __forceinline__ int perm_n(int cout) {
    int g = cout >> 6, fc = cout & 63;
    return (fc >> 3) * 32 + g * 8 + (fc & 7);
}

// step smem: A[0:46080) (180 rows x 256B, swizzled),
// B per-pair: pair nw at SB_BASE + nw*16384, stages +0 / +8192 (total 64KB)
#define SB_BASE 46080
#define ST_SMEM (SB_BASE + 4 * 16384)        // 111616
// ic smem: A x-tile 561 rows x 128B = 71808;
// B per-pair: pair nw at ICB_BASE + nw*8192, stages +0 / +4096 (total 32KB)
#define ICB_BASE 71808
#define IC_SMEM (ICB_BASE + 4 * 8192)        // 104576

// ---------------- prep ------------------------------------------------------
__global__ void prep_weights(const float* __restrict__ U,
                             const float* __restrict__ W,
                             const float* __restrict__ b) {
    int i = blockIdx.x * 256 + threadIdx.x;
    if (i < 9 * 64 * 256) {
        int tap = i / 16384, r = i % 16384, ci = r >> 8, cout = r & 255;
        g_ut[tap * 16384 + perm_n(cout) * 64 + ci] = to_tf32(U[i]);
    }
    if (i < 9 * 32 * 256) {
        int tap = i / 8192, r = i % 8192, ci = r >> 8, cout = r & 255;
        g_wt[tap * 8192 + perm_n(cout) * 32 + ci] = to_tf32(W[i]);
    }
    if (i < 256) g_bperm[perm_n(i)] = b[i];
}

// ---------------- input conv: per-pair B staging ----------------------------
// Producer (mw==0) fills its pair's 32-row B slice (4KB) per tap.
__device__ __forceinline__ void fill_icb_pair(unsigned dst, int tap, int nh,
                                              int nw, int lane) {
    const float* wt = g_wt + tap * 8192 + (nh * 128 + nw * 32) * 32;
#pragma unroll
    for (int i = lane; i < 256; i += 32) {
        int n = i >> 3, cc = i & 7;      // n 0..31 (slice-local), cc 0..7
        cp16p(dst + n * 128 + ((cc ^ (n & 7)) << 4), wt + n * 32 + cc * 4, true);
    }
    CP_COMMIT();
}

__global__ __launch_bounds__(256, 2) void ic_mma_kernel(
    const float* __restrict__ x, unsigned* __restrict__ xz)
{
    extern __shared__ __align__(1024) char smem[];
    unsigned sb = smem_u32(smem);
    const int tid = threadIdx.x, lane = tid & 31, wid = tid >> 5;
    const int mw = wid >> 2, nw = wid & 3;
    const int r = lane >> 2, cq = lane & 3;
    const int mt = blockIdx.x;
    const int img = blockIdx.y >> 1, nh = blockIdx.y & 1;
    const int oh0 = (mt >> 2) * 8, ow0 = (mt & 3) * 16;
    const int ih0 = 2 * oh0, iw0 = 2 * ow0;

    const unsigned pairB = sb + ICB_BASE + (unsigned)(nw * 8192);

    // A fill: 561 tile-rows x 8 chunks, raw fp32 x, zero-fill OOB; once
    for (int i = tid; i < 4488; i += 256) {
        int row = i >> 3, cc = i & 7;
        int trow = row / 33, tcol = row - trow * 33;
        int ih = ih0 + trow, iw = iw0 + tcol;
        bool ok = (ih < 128 && iw < 128);
        const float* s = x +
            (((size_t)img * 128 + (ok ? ih : 0)) * 128 + (ok ? iw : 0)) * 32 + cc * 4;
        cp16p(sb + row * 128 + ((cc ^ ((row >> 1) & 7)) << 4), s, ok);
    }
    if (mw == 0) fill_icb_pair(pairB, 0, nh, nw, lane);
    CP_COMMIT();
    CP_WAIT0();
    __syncthreads();                          // publish A + all pairs' B0

    unsigned nbase[4];
#pragma unroll
    for (int nf = 0; nf < 4; nf++)
        nbase[nf] = (unsigned)((nf * 8 + r) * 128 + cq * 4);   // slice-local

    float acc[4][4][4];
#pragma unroll
    for (int a = 0; a < 4; a++)
#pragma unroll
        for (int b = 0; b < 4; b++)
#pragma unroll
            for (int c = 0; c < 4; c++) acc[a][b][c] = 0.f;

    for (int tap = 0; tap < 9; tap++) {
        if (mw == 0 && tap < 8)
            fill_icb_pair(pairB + (unsigned)(((tap + 1) & 1) * 4096),
                          tap + 1, nh, nw, lane);
        const int kh = tap / 3, kw = tap - kh * 3;
        unsigned Bst = pairB + (unsigned)((tap & 1) * 4096);

        unsigned abase[4];
        int akey[4];
#pragma unroll
        for (int mf = 0; mf < 4; mf++) {
            int row0 = (2 * (mw * 4 + mf) + kh) * 33 + (2 * r + kw);
            abase[mf] = sb + (unsigned)(row0 * 128 + cq * 4);
            akey[mf] = (row0 >> 1) & 7;      // same key for row0+16
        }

#pragma unroll
        for (int k = 0; k < 4; k++) {
            unsigned av[4][4], bv[4][2];
#pragma unroll
            for (int mf = 0; mf < 4; mf++) {
                unsigned o0 = (unsigned)(((2 * k) ^ akey[mf]) << 4);
                av[mf][0] = cvt_tf32u(lds32(abase[mf] + o0));
                av[mf][1] = cvt_tf32u(lds32(abase[mf] + o0 + 2048));  // sc +8
                av[mf][2] = cvt_tf32u(lds32(abase[mf] + (o0 ^ 16)));
                av[mf][3] = cvt_tf32u(lds32(abase[mf] + (o0 ^ 16) + 2048));
            }
            {
                unsigned o0 = (unsigned)(((2 * k) ^ r) << 4);   // slice row&7 == r
#pragma unroll
                for (int nf = 0; nf < 4; nf++) {
                    bv[nf][0] = lds32(Bst + nbase[nf] + o0);
                    bv[nf][1] = lds32(Bst + nbase[nf] + (o0 ^ 16));
                }
            }
#pragma unroll
            for (int mf = 0; mf < 4; mf++)
#pragma unroll
                for (int nf = 0; nf < 4; nf++)
                    mma_tf32(acc[mf][nf], av[mf], bv[nf][0], bv[nf][1]);
        }

        if (tap < 8) {
            if (mw == 0) CP_WAIT0();          // pair's fill(tap+1) landed
            BAR_SYNC(nw + 1, 64);             // publish to consumer; reuse ok
        }
    }

    // epilogue: +bias(perm), pack rg pairs to half2, store fp16 blob
    float2 bvq[4];
#pragma unroll
    for (int nf = 0; nf < 4; nf++)
        bvq[nf] = *(const float2*)(g_bperm + nh * 128 + nw * 32 + nf * 8 + 2 * cq);
    unsigned* blob = xz + ((((size_t)img * 32 + mt) * 2 + nh) * 8 + wid) * 1024 + lane;
#pragma unroll
    for (int mf = 0; mf < 4; mf++)
#pragma unroll
        for (int nf = 0; nf < 4; nf++) {
            __half2 p0 = __floats2half2_rn(acc[mf][nf][0] + bvq[nf].x,
                                           acc[mf][nf][1] + bvq[nf].y);
            __half2 p1 = __floats2half2_rn(acc[mf][nf][2] + bvq[nf].x,
                                           acc[mf][nf][3] + bvq[nf].y);
            blob[((mf * 4 + nf) * 2 + 0) * 32] = *(unsigned*)&p0;
            blob[((mf * 4 + nf) * 2 + 1) * 32] = *(unsigned*)&p1;
        }
}

// ---------------- LSTM step: per-pair B staging + xz L2 prefetch ------------
__device__ __forceinline__ void fill_b_pair(unsigned dst, int tap, int nh,
                                            int nw, int lane) {
    const float* ut = g_ut + tap * 16384 + (nh * 128 + nw * 32) * 64;
#pragma unroll
    for (int i = lane; i < 512; i += 32) {
        int n = i >> 4, cc = i & 15;     // n 0..31, cc 0..15
        cp16p(dst + n * 256 + ((cc ^ (n & 7)) << 4), ut + n * 64 + cc * 4, true);
    }
    CP_COMMIT();
}

__global__ __launch_bounds__(256, 2) void lstm_step_mma(
    const float* __restrict__ hin, float* __restrict__ hout,
    float* __restrict__ cbuf, const unsigned* __restrict__ xz,
    const float* __restrict__ gamma, const float* __restrict__ beta,
    const float* __restrict__ mmean, const float* __restrict__ mvar,
    float* __restrict__ out, int t)
{
    extern __shared__ __align__(1024) char smem[];
    unsigned sb = smem_u32(smem);
    const int tid = threadIdx.x, lane = tid & 31, wid = tid >> 5;
    const int mw = wid >> 2, nw = wid & 3;
    const int r = lane >> 2, cq = lane & 3;
    const int mt = blockIdx.x;
    const int bb = blockIdx.y >> 1, nh = blockIdx.y & 1;
    const int oh0 = (mt >> 2) * 8, ow0 = (mt & 3) * 16;

    const unsigned pairB = sb + SB_BASE + (unsigned)(nw * 16384);

    // L2-prefetch this CTA's 32KB fp16 xz blob: 256 x 128B lines, 1/thread.
    {
        const unsigned* pf = xz +
            ((((size_t)(bb * TSTEPS + t) * 32 + mt) * 2 + nh) * 8) * 1024;
        l2_prefetch(pf + tid * 32);
    }

    // A: halo'd h tile 10x18 spatial rows x 256B (64ch fp32), swizzled; once
    for (int i = tid; i < 2880; i += 256) {
        int row = i >> 4, cc = i & 15;
        int sr = row / 18, sc = row - sr * 18;
        int ih = oh0 - 1 + sr, iw = ow0 - 1 + sc;
        bool ok = (ih >= 0 && ih < H2 && iw >= 0 && iw < W2);
        const float* s = hin +
            (((size_t)bb * H2 + (ok ? ih : 0)) * W2 + (ok ? iw : 0)) * FCH + cc * 4;
        cp16p(sb + row * 256 + ((cc ^ (row & 7)) << 4), s, ok);
    }
    if (mw == 0) fill_b_pair(pairB, 0, nh, nw, lane);
    CP_COMMIT();
    CP_WAIT0();
    __syncthreads();                          // publish A + all pairs' B0

    unsigned nbase[4];
#pragma unroll
    for (int nf = 0; nf < 4; nf++)
        nbase[nf] = (unsigned)((nf * 8 + r) * 256 + cq * 4);   // slice-local

    float acc[4][4][4];
#pragma unroll
    for (int a = 0; a < 4; a++)
#pragma unroll
        for (int b = 0; b < 4; b++)
#pragma unroll
            for (int c = 0; c < 4; c++) acc[a][b][c] = 0.f;

    for (int tap = 0; tap < 9; tap++) {
        if (mw == 0 && tap < 8)
            fill_b_pair(pairB + (unsigned)(((tap + 1) & 1) * 8192),
                        tap + 1, nh, nw, lane);
        const int kh = tap / 3, kw = tap - kh * 3;
        unsigned Bst = pairB + (unsigned)((tap & 1) * 8192);

        unsigned abase[4];
        int ar7[4];
#pragma unroll
        for (int mf = 0; mf < 4; mf++) {
            int row0 = (mw * 4 + mf + kh) * 18 + r + kw;
            abase[mf] = sb + (unsigned)(row0 * 256 + cq * 4);
            ar7[mf] = row0 & 7;
        }

#pragma unroll
        for (int k = 0; k < 8; k++) {
            unsigned av[4][4], bv[4][2];
#pragma unroll
            for (int mf = 0; mf < 4; mf++) {
                unsigned o0 = (unsigned)(((2 * k) ^ ar7[mf]) << 4);
                av[mf][0] = lds32(abase[mf] + o0);
                av[mf][1] = lds32(abase[mf] + o0 + 2048);       // ow +8
                av[mf][2] = lds32(abase[mf] + (o0 ^ 16));
                av[mf][3] = lds32(abase[mf] + (o0 ^ 16) + 2048);
            }
            {
                unsigned o0 = (unsigned)(((2 * k) ^ r) << 4);   // slice row&7 == r
#pragma unroll
                for (int nf = 0; nf < 4; nf++) {
                    bv[nf][0] = lds32(Bst + nbase[nf] + o0);
                    bv[nf][1] = lds32(Bst + nbase[nf] + (o0 ^ 16));
                }
            }
#pragma unroll
            for (int mf = 0; mf < 4; mf++)
#pragma unroll
                for (int nf = 0; nf < 4; nf++)
                    mma_tf32(acc[mf][nf], av[mf], bv[nf][0], bv[nf][1]);
        }

        if (tap < 8) {
            if (mw == 0) CP_WAIT0();          // pair's fill(tap+1) landed
            BAR_SYNC(nw + 1, 64);             // publish to consumer; reuse ok
        }
    }

    // add xz (bias folded) from fp16 blob — L2-hot from the prefetch
    const unsigned* blob = xz +
        ((((size_t)(bb * TSTEPS + t) * 32 + mt) * 2 + nh) * 8 + wid) * 1024 + lane;
#pragma unroll
    for (int mf = 0; mf < 4; mf++)
#pragma unroll
        for (int nf = 0; nf < 4; nf++)
#pragma unroll
            for (int rgp = 0; rgp < 2; rgp++) {
                unsigned u = blob[((mf * 4 + nf) * 2 + rgp) * 32];
                float2 f = __half22float2(*(__half2*)&u);
                acc[mf][nf][2 * rgp]     += f.x;
                acc[mf][nf][2 * rgp + 1] += f.y;
            }

    // gates in-register: nf = gate; lane fc pair fc0, fc0+1
    const int fc0 = (nh * 4 + nw) * 8 + 2 * cq;
    float2 gm = *(const float2*)(gamma + fc0);
    float2 bt = *(const float2*)(beta + fc0);
    float2 mu = *(const float2*)(mmean + fc0);
    float2 vr = *(const float2*)(mvar + fc0);
    float sc0 = gm.x * rsqrtf(vr.x + 1e-3f);
    float sc1 = gm.y * rsqrtf(vr.y + 1e-3f);

#pragma unroll
    for (int mf = 0; mf < 4; mf++) {
        int oh = oh0 + mw * 4 + mf;
#pragma unroll
        for (int rh = 0; rh < 2; rh++) {
            int ow = ow0 + r + 8 * rh;
            size_t sidx = (((size_t)bb * H2 + oh) * W2 + ow) * FCH + fc0;
            float2 cc2 = *(const float2*)(cbuf + sidx);
            float cn[2], hn[2], ov[2];
#pragma unroll
            for (int q = 0; q < 2; q++) {
                float zi = acc[mf][0][2 * rh + q];
                float zf = acc[mf][1][2 * rh + q];
                float zg = acc[mf][2][2 * rh + q];
                float zo = acc[mf][3][2 * rh + q];
                float co = q ? cc2.y : cc2.x;
                float c2 = hsig(zf) * co + hsig(zi) * tanhf(zg);
                hn[q] = hsig(zo) * tanhf(c2);
                cn[q] = c2;
                float s = q ? sc1 : sc0;
                ov[q] = (hn[q] - (q ? mu.y : mu.x)) * s + (q ? bt.y : bt.x);
            }
            *(float2*)(cbuf + sidx) = make_float2(cn[0], cn[1]);
            *(float2*)(hout + sidx) = make_float2(to_tf32(hn[0]), to_tf32(hn[1]));
            *(float2*)(out + ((((size_t)bb * TSTEPS + t) * H2 + oh) * W2 + ow) * FCH + fc0)
                = make_float2(ov[0], ov[1]);
        }
    }
}

// ---------------------------------------------------------------------------
extern "C" void kernel_launch(void* const* d_in, const int* in_sizes, int n_in,
                              void* d_out, int out_size)
{
    const float* x     = (const float*)d_in[0];
    const float* W     = (const float*)d_in[1];
    const float* U     = (const float*)d_in[2];
    const float* b     = (const float*)d_in[3];
    const float* gamma = (const float*)d_in[4];
    const float* beta  = (const float*)d_in[5];
    const float* mm    = (const float*)d_in[6];
    const float* mv    = (const float*)d_in[7];
    float* out = (float*)d_out;

    unsigned* xz;
    float *cbuf, *hbuf;
    cudaGetSymbolAddress((void**)&xz, g_xz);
    cudaGetSymbolAddress((void**)&cbuf, g_c);
    cudaGetSymbolAddress((void**)&hbuf, g_ht);
    const size_t hsz = (size_t)BATCH * H2 * W2 * FCH;

    cudaFuncSetAttribute(ic_mma_kernel,
                         cudaFuncAttributeMaxDynamicSharedMemorySize, IC_SMEM);
    cudaFuncSetAttribute(lstm_step_mma,
                         cudaFuncAttributeMaxDynamicSharedMemorySize, ST_SMEM);

    cudaMemsetAsync(hbuf, 0, hsz * sizeof(float));
    cudaMemsetAsync(cbuf, 0, hsz * sizeof(float));

    prep_weights<<<576, 256>>>(U, W, b);
    ic_mma_kernel<<<dim3(32, 128), 256, IC_SMEM>>>(x, xz);

    for (int t = 0; t < TSTEPS; t++) {
        int rd = t & 1, wr = (t + 1) & 1;
        lstm_step_mma<<<dim3(32, 8), 256, ST_SMEM>>>(
            hbuf + rd * hsz, hbuf + wr * hsz,
            cbuf, xz, gamma, beta, mm, mv, out, t);
    }
}